// round 5
// baseline (speedup 1.0000x reference)
#include <cuda_runtime.h>
#include <math.h>

#define Bsz 64
#define TT 512
#define DD 512
#define HH 512
#define G4 2048   // 4*H
#define NCTA 128

// Scratch (static device globals are the sanctioned scratch mechanism)
__device__ float g_xz[2][TT][G4][Bsz];      // [dir][t][gatecol][b]  (512 MB)
__device__ float g_hbuf[2][2][Bsz][HH];     // [buf][dir][b][hidx]  (b-major!)
__device__ unsigned g_cnt;                  // barrier arrivals
__device__ volatile unsigned g_phase;       // barrier phase (reset at kernel end)

// ---------------------------------------------------------------------------
// tf32 helpers
// ---------------------------------------------------------------------------
__device__ __forceinline__ unsigned f2tf(float f) {
    unsigned r;
    asm("cvt.rna.tf32.f32 %0, %1;" : "=r"(r) : "f"(f));
    return r;
}

__device__ __forceinline__ void mma1688(float c[4],
                                        unsigned a0, unsigned a1, unsigned a2, unsigned a3,
                                        unsigned b0, unsigned b1) {
    asm volatile(
        "mma.sync.aligned.m16n8k8.row.col.f32.tf32.tf32.f32 "
        "{%0,%1,%2,%3}, {%4,%5,%6,%7}, {%8,%9}, {%0,%1,%2,%3};\n"
        : "+f"(c[0]), "+f"(c[1]), "+f"(c[2]), "+f"(c[3])
        : "r"(a0), "r"(a1), "r"(a2), "r"(a3), "r"(b0), "r"(b1));
}

__device__ __forceinline__ void cp16(unsigned saddr, const void* g) {
    asm volatile("cp.async.cg.shared.global [%0], [%1], 16;" :: "r"(saddr), "l"(g));
}
__device__ __forceinline__ void cp_commit() {
    asm volatile("cp.async.commit_group;");
}
template <int N>
__device__ __forceinline__ void cp_wait() {
    asm volatile("cp.async.wait_group %0;" :: "n"(N));
}

// ---------------------------------------------------------------------------
// Kernel 1: input projection via tf32 tensor-core MMA (unchanged from R2).
// ---------------------------------------------------------------------------
#define W_PITCH 264
#define X_PITCH 36
#define W_ELEMS (32 * W_PITCH)
#define X_ELEMS (64 * X_PITCH)
#define PROJ_SMEM ((W_ELEMS + 2 * X_ELEMS) * 4)

__global__ __launch_bounds__(512, 1) void proj_mma_kernel(
    const float* __restrict__ x,
    const float* __restrict__ Wfk, const float* __restrict__ bf,
    const float* __restrict__ Wbk, const float* __restrict__ bb)
{
    extern __shared__ unsigned psm[];
    unsigned* w_s = psm;                 // [32][W_PITCH]  (k x col)
    unsigned* x_s = psm + W_ELEMS;       // [2][64][X_PITCH] (ts x b x k)

    const int tid = threadIdx.x;
    const int colTile = blockIdx.x;      // 0..7
    const int tpair = blockIdx.y;        // 0..255
    const int dir = blockIdx.z;          // 0..1
    const int colbase = colTile * 256;
    const float* __restrict__ Wk = dir ? Wbk : Wfk;
    const float* __restrict__ bias = dir ? bb : bf;

    const int lane = tid & 31;
    const int grp = lane >> 2;
    const int tig = lane & 3;
    const int wid = tid >> 5;
    const int wn = wid & 1;
    const int wm = wid >> 1;

    float acc[2][2][4][4];
    #pragma unroll
    for (int a = 0; a < 2; a++)
        #pragma unroll
        for (int b = 0; b < 2; b++)
            #pragma unroll
            for (int c = 0; c < 4; c++)
                #pragma unroll
                for (int d = 0; d < 4; d++) acc[a][b][c][d] = 0.f;

    #pragma unroll 1
    for (int k0 = 0; k0 < DD; k0 += 32) {
        __syncthreads();
        #pragma unroll
        for (int j = 0; j < 4; j++) {
            int e4 = tid + j * 512;
            int kk = e4 >> 6;
            int cc = (e4 & 63) * 4;
            float4 v = *(const float4*)(Wk + (size_t)(k0 + kk) * G4 + colbase + cc);
            uint4 u = make_uint4(f2tf(v.x), f2tf(v.y), f2tf(v.z), f2tf(v.w));
            *(uint4*)(w_s + kk * W_PITCH + cc) = u;
        }
        #pragma unroll
        for (int j = 0; j < 2; j++) {
            int f4 = tid + j * 512;
            int ts = f4 >> 9;
            int r = f4 & 511;
            int b = r >> 3;
            int kc4 = (r & 7) * 4;
            int t = tpair * 2 + ts;
            float4 v = *(const float4*)(x + ((size_t)b * TT + t) * DD + k0 + kc4);
            uint4 u = make_uint4(f2tf(v.x), f2tf(v.y), f2tf(v.z), f2tf(v.w));
            *(uint4*)(x_s + ts * X_ELEMS + b * X_PITCH + kc4) = u;
        }
        __syncthreads();

        #pragma unroll
        for (int ks = 0; ks < 4; ks++) {
            const int kr = ks * 8;
            unsigned a[2][4];
            #pragma unroll
            for (int mt = 0; mt < 2; mt++) {
                int cb = wm * 32 + mt * 16 + grp;
                a[mt][0] = w_s[(kr + tig) * W_PITCH + cb];
                a[mt][1] = w_s[(kr + tig) * W_PITCH + cb + 8];
                a[mt][2] = w_s[(kr + tig + 4) * W_PITCH + cb];
                a[mt][3] = w_s[(kr + tig + 4) * W_PITCH + cb + 8];
            }
            unsigned bb_[2][4][2];
            #pragma unroll
            for (int ts = 0; ts < 2; ts++)
                #pragma unroll
                for (int nt = 0; nt < 4; nt++) {
                    int idx = ts * X_ELEMS + (wn * 32 + nt * 8 + grp) * X_PITCH + kr + tig;
                    bb_[ts][nt][0] = x_s[idx];
                    bb_[ts][nt][1] = x_s[idx + 4];
                }
            #pragma unroll
            for (int ts = 0; ts < 2; ts++)
                #pragma unroll
                for (int mt = 0; mt < 2; mt++)
                    #pragma unroll
                    for (int nt = 0; nt < 4; nt++)
                        mma1688(acc[ts][mt][nt],
                                a[mt][0], a[mt][1], a[mt][2], a[mt][3],
                                bb_[ts][nt][0], bb_[ts][nt][1]);
        }
    }

    #pragma unroll
    for (int ts = 0; ts < 2; ts++) {
        int t = tpair * 2 + ts;
        float* gx = &g_xz[dir][t][0][0];
        #pragma unroll
        for (int mt = 0; mt < 2; mt++) {
            int col = colbase + wm * 32 + mt * 16 + grp;
            float bv = bias[col];
            float bv8 = bias[col + 8];
            #pragma unroll
            for (int nt = 0; nt < 4; nt++) {
                int b = wn * 32 + nt * 8 + tig * 2;
                float2 lo = make_float2(acc[ts][mt][nt][0] + bv,
                                        acc[ts][mt][nt][1] + bv);
                float2 hi = make_float2(acc[ts][mt][nt][2] + bv8,
                                        acc[ts][mt][nt][3] + bv8);
                *(float2*)(gx + (size_t)col * Bsz + b) = lo;
                *(float2*)(gx + (size_t)(col + 8) * Bsz + b) = hi;
            }
        }
    }
}

// ---------------------------------------------------------------------------
// Kernel 2: persistent bidirectional LSTM scan, split-tf32 MMA.
// R5: b-major h staging (pitch 132) -> conflict-free B-fragment LDS;
//     g_hbuf flipped to [b][h]; float2 publishes/outputs.
// ---------------------------------------------------------------------------
__device__ __forceinline__ float sigf(float v) { return 1.f / (1.f + __expf(-v)); }

// Wpack: [term(hi=0,lo=1)][wm(2)][kstep(64)][lane(32)][4]
#define WPK_TERM (2 * 64 * 32 * 4)   // 16384 floats per term
#define WPK_TOTAL (2 * WPK_TERM)     // 32768 floats (128 KB)
#define H_PITCH 132                  // floats; 132 mod 32 == 4 -> conflict-free
#define HS_CHUNK (64 * H_PITCH)      // 8448 floats per chunk buffer
// SMEM floats: Wpack 32768, hs 2*8448, zx 2*2048, zbuf 2048
#define SCAN_SMEM ((WPK_TOTAL + 2 * HS_CHUNK + 2 * 2048 + 2048) * 4)

__global__ __launch_bounds__(256, 1) void scan_mma_kernel(
    const float* __restrict__ Wfr, const float* __restrict__ Wbr,
    float* __restrict__ out)
{
    extern __shared__ float smem[];
    float* Wpack = smem;                      // fragment-packed hi/lo
    float* hs  = smem + WPK_TOTAL;            // [2][64][H_PITCH]
    float* zx  = hs + 2 * HS_CHUNK;           // [2][32][64]
    float* zbuf = zx + 2 * 2048;              // [32][64]

    const int tx = threadIdx.x;
    const int cta = blockIdx.x;        // 0..127
    const int dir = cta >> 6;
    const int hbase = (cta & 63) * 8;
    const float* __restrict__ Wr = dir ? Wbr : Wfr;

    // Pre-split + fragment-pack resident Wr slice.
    for (int e = tx; e < WPK_TERM; e += 256) {
        int j = e & 3;
        int lane = (e >> 2) & 31;
        int kstep = (e >> 7) & 63;
        int wmi = e >> 13;
        int grp = lane >> 2, tig = lane & 3;
        int m = wmi * 16 + grp + ((j & 1) ? 8 : 0);
        int k = kstep * 8 + tig + ((j & 2) ? 4 : 0);
        int gate = m >> 3, jc = m & 7;
        float w = Wr[(size_t)k * G4 + gate * HH + hbase + jc];
        unsigned hi = f2tf(w);
        float lo = w - __uint_as_float(hi);
        Wpack[e] = __uint_as_float(hi);
        Wpack[WPK_TERM + e] = __uint_as_float(f2tf(lo));
    }

    // Zero our slice of h buffer 0 (layout [b][h])
    for (int idx = tx; idx < 8 * 64; idx += 256) {
        int b = idx >> 3, hj = idx & 7;
        g_hbuf[0][dir][b][hbase + hj] = 0.f;
    }

    // Warp layout for MMA
    const int lane = tx & 31;
    const int warp = tx >> 5;
    const int wm = warp >> 2;          // 0..1, m0 = wm*16
    const int n0 = (warp & 3) * 16;    // n (batch) base
    const int grp = lane >> 2;         // 0..7
    const int tig = lane & 3;          // 0..3

    // Gate-phase mapping: thread owns (b_p, hj0) and (b_p, hj0+1)
    const int b_p = tx >> 2;           // 0..63
    const int hj0 = (tx & 3) * 2;      // 0,2,4,6
    float c_reg0 = 0.f, c_reg1 = 0.f;

    const unsigned hs_addr = (unsigned)__cvta_generic_to_shared(hs);
    const unsigned zx_addr = (unsigned)__cvta_generic_to_shared(zx);

    float* out_sent = out + (size_t)Bsz * TT * (2 * HH);

    // Barrier init visibility
    __syncthreads();
    if (tx == 0) {
        __threadfence();
        unsigned old = atomicAdd(&g_cnt, 1u);
        if (old == NCTA - 1) { g_cnt = 0; __threadfence(); g_phase = 1; }
        else { while (g_phase < 1u) { } }
        __threadfence();
    }
    __syncthreads();

    // Prefetch zx[t=0] into buffer 0
    {
        const float* xzb = &g_xz[dir][dir ? (TT - 1) : 0][0][0];
        #pragma unroll
        for (int i = 0; i < 2; i++) {
            int s = tx + i * 256;
            int c = s >> 4, off = (s & 15) * 4;
            int gate = c >> 3, jj = c & 7;
            cp16(zx_addr + (c * 64 + off) * 4,
                 xzb + (size_t)(gate * HH + hbase + jj) * Bsz + off);
        }
        cp_commit();
    }

    // Staging thread mapping: f4 -> (b = f4>>5, kq = (f4&31)*4)
    const int st_b = tx >> 2;                // reused per i-offset below

    for (int t = 0; t < TT; t++) {
        const int rb = t & 1, wb = (t + 1) & 1;
        const int tq = dir ? (TT - 1 - t) : t;
        const int zb = t & 1;
        const float* hsrc = &g_hbuf[rb][dir][0][0];    // [64][512]

        // Issue h chunks 0 and 1 (k-ranges, double-buffered)
        #pragma unroll
        for (int i = 0; i < 8; i++) {
            int f4 = tx + i * 256;            // 0..2047
            int b = f4 >> 5;
            int kq = (f4 & 31) * 4;
            cp16(hs_addr + (b * H_PITCH + kq) * 4, hsrc + b * 512 + kq);
        }
        cp_commit();
        #pragma unroll
        for (int i = 0; i < 8; i++) {
            int f4 = tx + i * 256;
            int b = f4 >> 5;
            int kq = (f4 & 31) * 4;
            cp16(hs_addr + (HS_CHUNK + b * H_PITCH + kq) * 4,
                 hsrc + b * 512 + 128 + kq);
        }
        cp_commit();

        float acc[2][4];
        #pragma unroll
        for (int nt = 0; nt < 2; nt++)
            #pragma unroll
            for (int d = 0; d < 4; d++) acc[nt][d] = 0.f;

        #pragma unroll 1
        for (int ch = 0; ch < 4; ch++) {
            if (ch < 3) cp_wait<1>(); else cp_wait<0>();
            __syncthreads();
            const float* hc = hs + (ch & 1) * HS_CHUNK;
            const float* WH = Wpack + (wm * 64 + ch * 16) * 128;
            const float* WL = WH + WPK_TERM;

            #pragma unroll
            for (int ks = 0; ks < 16; ks++) {
                const int kr = ks * 8;
                uint4 AH = *(const uint4*)(WH + ks * 128 + lane * 4);
                uint4 AL = *(const uint4*)(WL + ks * 128 + lane * 4);
                #pragma unroll
                for (int nt = 0; nt < 2; nt++) {
                    const float* hb = hc + (n0 + nt * 8 + grp) * H_PITCH + kr;
                    float f0 = hb[tig];
                    float f1 = hb[tig + 4];
                    unsigned bh0 = f2tf(f0);
                    unsigned bh1 = f2tf(f1);
                    unsigned bl0 = f2tf(f0 - __uint_as_float(bh0));
                    unsigned bl1 = f2tf(f1 - __uint_as_float(bh1));
                    mma1688(acc[nt], AH.x, AH.y, AH.z, AH.w, bh0, bh1);
                    mma1688(acc[nt], AL.x, AL.y, AL.z, AL.w, bh0, bh1);
                    mma1688(acc[nt], AH.x, AH.y, AH.z, AH.w, bl0, bl1);
                }
            }
            __syncthreads();   // chunk reads done before buffer reuse
            if (ch < 2) {      // issue chunk ch+2 into buffer (ch&1)
                const float* src = hsrc + (ch + 2) * 128;
                unsigned dstb = hs_addr + (ch & 1) * HS_CHUNK * 4;
                #pragma unroll
                for (int i = 0; i < 8; i++) {
                    int f4 = tx + i * 256;
                    int b = f4 >> 5;
                    int kq = (f4 & 31) * 4;
                    cp16(dstb + (b * H_PITCH + kq) * 4, src + b * 512 + kq);
                }
                // Fold next-step zx prefetch into the second refill group
                if (ch == 1 && t < TT - 1) {
                    const int tq2 = dir ? (TT - 2 - t) : (t + 1);
                    const float* xzb = &g_xz[dir][tq2][0][0];
                    unsigned zdst = zx_addr + ((t + 1) & 1) * 2048 * 4;
                    #pragma unroll
                    for (int i = 0; i < 2; i++) {
                        int s = tx + i * 256;
                        int c = s >> 4, off = (s & 15) * 4;
                        int gate = c >> 3, jj = c & 7;
                        cp16(zdst + (c * 64 + off) * 4,
                             xzb + (size_t)(gate * HH + hbase + jj) * Bsz + off);
                    }
                }
                cp_commit();
            }
        }

        // Write acc into zbuf[c][b]  (c = m index = gate*8+j)
        {
            int m0 = wm * 16;
            #pragma unroll
            for (int nt = 0; nt < 2; nt++) {
                int n = n0 + nt * 8 + tig * 2;
                *(float2*)&zbuf[(m0 + grp) * 64 + n] =
                    make_float2(acc[nt][0], acc[nt][1]);
                *(float2*)&zbuf[(m0 + grp + 8) * 64 + n] =
                    make_float2(acc[nt][2], acc[nt][3]);
            }
        }
        __syncthreads();

        // Gate phase: thread finishes (hj0, b_p) and (hj0+1, b_p)
        const float* zxc = zx + zb * 2048;
        float z0[4], z1[4];
        #pragma unroll
        for (int gate = 0; gate < 4; gate++) {
            int c0i = (gate * 8 + hj0) * 64 + b_p;
            int c1i = (gate * 8 + hj0 + 1) * 64 + b_p;
            z0[gate] = zxc[c0i] + zbuf[c0i];
            z1[gate] = zxc[c1i] + zbuf[c1i];
        }
        float i0 = sigf(z0[0]), f0 = sigf(z0[1]), g0 = tanhf(z0[2]), o0 = sigf(z0[3]);
        c_reg0 = f0 * c_reg0 + i0 * g0;
        float h0v = o0 * tanhf(c_reg0);
        float i1 = sigf(z1[0]), f1 = sigf(z1[1]), g1 = tanhf(z1[2]), o1 = sigf(z1[3]);
        c_reg1 = f1 * c_reg1 + i1 * g1;
        float h1v = o1 * tanhf(c_reg1);

        // Publish h (float2, dense 32B segments) — must precede arrive
        *(float2*)&g_hbuf[wb][dir][b_p][hbase + hj0] = make_float2(h0v, h1v);

        if (t < TT - 1) {
            // ---- barrier ARRIVE ----
            __syncthreads();
            if (tx == 0) {
                __threadfence();
                unsigned old = atomicAdd(&g_cnt, 1u);
                if (old == NCTA - 1) {
                    g_cnt = 0;
                    __threadfence();
                    g_phase = (unsigned)(t + 2);
                }
            }
            // ---- scattered output stores overlap the wait ----
            size_t wo = ((size_t)b_p * TT + tq) * (2 * HH) + dir * HH + hbase + hj0;
            *(float2*)(out + wo) = make_float2(h0v, h1v);
            // ---- barrier WAIT ----
            if (tx == 0) {
                while (g_phase < (unsigned)(t + 2)) { }
                __threadfence();
            }
            __syncthreads();
        } else {
            size_t wo = ((size_t)b_p * TT + tq) * (2 * HH) + dir * HH + hbase + hj0;
            *(float2*)(out + wo) = make_float2(h0v, h1v);
            size_t so = (size_t)b_p * (2 * HH) + dir * HH + hbase + hj0;
            *(float2*)(out_sent + so) = make_float2(h0v, h1v);
        }
    }

    // Reset barrier state for next graph replay
    __syncthreads();
    if (tx == 0) {
        __threadfence();
        unsigned old = atomicAdd(&g_cnt, 1u);
        if (old == NCTA - 1) {
            g_cnt = 0;
            __threadfence();
            g_phase = 0;
        }
    }
}

// ---------------------------------------------------------------------------
extern "C" void kernel_launch(void* const* d_in, const int* in_sizes, int n_in,
                              void* d_out, int out_size) {
    const float* x   = (const float*)d_in[0];
    const float* Wfk = (const float*)d_in[1];
    const float* Wfr = (const float*)d_in[2];
    const float* bf  = (const float*)d_in[3];
    const float* Wbk = (const float*)d_in[4];
    const float* Wbr = (const float*)d_in[5];
    const float* bb  = (const float*)d_in[6];
    float* out = (float*)d_out;

    cudaFuncSetAttribute(scan_mma_kernel,
                         cudaFuncAttributeMaxDynamicSharedMemorySize, SCAN_SMEM);
    cudaFuncSetAttribute(proj_mma_kernel,
                         cudaFuncAttributeMaxDynamicSharedMemorySize, PROJ_SMEM);

    dim3 pg(8, 256, 2);
    proj_mma_kernel<<<pg, 512, PROJ_SMEM>>>(x, Wfk, bf, Wbk, bb);
    scan_mma_kernel<<<NCTA, 256, SCAN_SMEM>>>(Wfr, Wbr, out);
}

// round 6
// speedup vs baseline: 1.4981x; 1.4981x over previous
#include <cuda_runtime.h>
#include <math.h>

#define Bsz 64
#define TT 512
#define DD 512
#define HH 512
#define G4 2048   // 4*H
#define NCTA 128

// Scratch (static device globals are the sanctioned scratch mechanism)
__device__ float g_xz[2][TT][G4][Bsz];      // [dir][t][gatecol][b]  (512 MB)
__device__ float g_hbuf[2][2][HH][Bsz];     // [buf][dir][hidx][b]
__device__ unsigned g_cnt;                  // barrier arrivals
__device__ volatile unsigned g_phase;       // barrier phase (reset at kernel end)

// ---------------------------------------------------------------------------
// tf32 helpers
// ---------------------------------------------------------------------------
__device__ __forceinline__ unsigned f2tf(float f) {
    unsigned r;
    asm("cvt.rna.tf32.f32 %0, %1;" : "=r"(r) : "f"(f));
    return r;
}

__device__ __forceinline__ void mma1688(float c[4],
                                        unsigned a0, unsigned a1, unsigned a2, unsigned a3,
                                        unsigned b0, unsigned b1) {
    asm volatile(
        "mma.sync.aligned.m16n8k8.row.col.f32.tf32.tf32.f32 "
        "{%0,%1,%2,%3}, {%4,%5,%6,%7}, {%8,%9}, {%0,%1,%2,%3};\n"
        : "+f"(c[0]), "+f"(c[1]), "+f"(c[2]), "+f"(c[3])
        : "r"(a0), "r"(a1), "r"(a2), "r"(a3), "r"(b0), "r"(b1));
}

__device__ __forceinline__ void cp16(unsigned saddr, const void* g) {
    asm volatile("cp.async.cg.shared.global [%0], [%1], 16;" :: "r"(saddr), "l"(g));
}
__device__ __forceinline__ void cp_commit() {
    asm volatile("cp.async.commit_group;");
}
template <int N>
__device__ __forceinline__ void cp_wait() {
    asm volatile("cp.async.wait_group %0;" :: "n"(N));
}

// ---------------------------------------------------------------------------
// Kernel 1: input projection via tf32 tensor-core MMA (unchanged from R2).
// ---------------------------------------------------------------------------
#define W_PITCH 264
#define X_PITCH 36
#define W_ELEMS (32 * W_PITCH)
#define X_ELEMS (64 * X_PITCH)
#define PROJ_SMEM ((W_ELEMS + 2 * X_ELEMS) * 4)

__global__ __launch_bounds__(512, 1) void proj_mma_kernel(
    const float* __restrict__ x,
    const float* __restrict__ Wfk, const float* __restrict__ bf,
    const float* __restrict__ Wbk, const float* __restrict__ bb)
{
    extern __shared__ unsigned psm[];
    unsigned* w_s = psm;                 // [32][W_PITCH]  (k x col)
    unsigned* x_s = psm + W_ELEMS;       // [2][64][X_PITCH] (ts x b x k)

    const int tid = threadIdx.x;
    const int colTile = blockIdx.x;      // 0..7
    const int tpair = blockIdx.y;        // 0..255
    const int dir = blockIdx.z;          // 0..1
    const int colbase = colTile * 256;
    const float* __restrict__ Wk = dir ? Wbk : Wfk;
    const float* __restrict__ bias = dir ? bb : bf;

    const int lane = tid & 31;
    const int grp = lane >> 2;
    const int tig = lane & 3;
    const int wid = tid >> 5;
    const int wn = wid & 1;
    const int wm = wid >> 1;

    float acc[2][2][4][4];
    #pragma unroll
    for (int a = 0; a < 2; a++)
        #pragma unroll
        for (int b = 0; b < 2; b++)
            #pragma unroll
            for (int c = 0; c < 4; c++)
                #pragma unroll
                for (int d = 0; d < 4; d++) acc[a][b][c][d] = 0.f;

    #pragma unroll 1
    for (int k0 = 0; k0 < DD; k0 += 32) {
        __syncthreads();
        #pragma unroll
        for (int j = 0; j < 4; j++) {
            int e4 = tid + j * 512;
            int kk = e4 >> 6;
            int cc = (e4 & 63) * 4;
            float4 v = *(const float4*)(Wk + (size_t)(k0 + kk) * G4 + colbase + cc);
            uint4 u = make_uint4(f2tf(v.x), f2tf(v.y), f2tf(v.z), f2tf(v.w));
            *(uint4*)(w_s + kk * W_PITCH + cc) = u;
        }
        #pragma unroll
        for (int j = 0; j < 2; j++) {
            int f4 = tid + j * 512;
            int ts = f4 >> 9;
            int r = f4 & 511;
            int b = r >> 3;
            int kc4 = (r & 7) * 4;
            int t = tpair * 2 + ts;
            float4 v = *(const float4*)(x + ((size_t)b * TT + t) * DD + k0 + kc4);
            uint4 u = make_uint4(f2tf(v.x), f2tf(v.y), f2tf(v.z), f2tf(v.w));
            *(uint4*)(x_s + ts * X_ELEMS + b * X_PITCH + kc4) = u;
        }
        __syncthreads();

        #pragma unroll
        for (int ks = 0; ks < 4; ks++) {
            const int kr = ks * 8;
            unsigned a[2][4];
            #pragma unroll
            for (int mt = 0; mt < 2; mt++) {
                int cb = wm * 32 + mt * 16 + grp;
                a[mt][0] = w_s[(kr + tig) * W_PITCH + cb];
                a[mt][1] = w_s[(kr + tig) * W_PITCH + cb + 8];
                a[mt][2] = w_s[(kr + tig + 4) * W_PITCH + cb];
                a[mt][3] = w_s[(kr + tig + 4) * W_PITCH + cb + 8];
            }
            unsigned bb_[2][4][2];
            #pragma unroll
            for (int ts = 0; ts < 2; ts++)
                #pragma unroll
                for (int nt = 0; nt < 4; nt++) {
                    int idx = ts * X_ELEMS + (wn * 32 + nt * 8 + grp) * X_PITCH + kr + tig;
                    bb_[ts][nt][0] = x_s[idx];
                    bb_[ts][nt][1] = x_s[idx + 4];
                }
            #pragma unroll
            for (int ts = 0; ts < 2; ts++)
                #pragma unroll
                for (int mt = 0; mt < 2; mt++)
                    #pragma unroll
                    for (int nt = 0; nt < 4; nt++)
                        mma1688(acc[ts][mt][nt],
                                a[mt][0], a[mt][1], a[mt][2], a[mt][3],
                                bb_[ts][nt][0], bb_[ts][nt][1]);
        }
    }

    #pragma unroll
    for (int ts = 0; ts < 2; ts++) {
        int t = tpair * 2 + ts;
        float* gx = &g_xz[dir][t][0][0];
        #pragma unroll
        for (int mt = 0; mt < 2; mt++) {
            int col = colbase + wm * 32 + mt * 16 + grp;
            float bv = bias[col];
            float bv8 = bias[col + 8];
            #pragma unroll
            for (int nt = 0; nt < 4; nt++) {
                int b = wn * 32 + nt * 8 + tig * 2;
                float2 lo = make_float2(acc[ts][mt][nt][0] + bv,
                                        acc[ts][mt][nt][1] + bv);
                float2 hi = make_float2(acc[ts][mt][nt][2] + bv8,
                                        acc[ts][mt][nt][3] + bv8);
                *(float2*)(gx + (size_t)col * Bsz + b) = lo;
                *(float2*)(gx + (size_t)(col + 8) * Bsz + b) = hi;
            }
        }
    }
}

// ---------------------------------------------------------------------------
// Kernel 2: persistent bidirectional LSTM scan, split-tf32 MMA.
// R6 = R4 + padded h-staging pitch (64 -> 72) for conflict-free B LDS.
// ---------------------------------------------------------------------------
__device__ __forceinline__ float sigf(float v) { return 1.f / (1.f + __expf(-v)); }

// Wpack: [term(hi=0,lo=1)][wm(2)][kstep(64)][lane(32)][4]
#define WPK_TERM (2 * 64 * 32 * 4)   // 16384 floats per term
#define WPK_TOTAL (2 * WPK_TERM)     // 32768 floats (128 KB)
#define HB_PITCH 72                  // floats; 72 mod 32 == 8 -> conflict-free
#define HS_CHUNK (128 * HB_PITCH)    // 9216 floats per chunk buffer
// SMEM floats: Wpack 32768, hs 2*9216, zx 2*2048, zbuf 2048 = 57344 (224 KB)
#define SCAN_SMEM ((WPK_TOTAL + 2 * HS_CHUNK + 2 * 2048 + 2048) * 4)

__global__ __launch_bounds__(256, 1) void scan_mma_kernel(
    const float* __restrict__ Wfr, const float* __restrict__ Wbr,
    float* __restrict__ out)
{
    extern __shared__ float smem[];
    float* Wpack = smem;                      // fragment-packed hi/lo
    float* hs  = smem + WPK_TOTAL;            // [2][128][HB_PITCH]
    float* zx  = hs + 2 * HS_CHUNK;           // [2][32][64]
    float* zbuf = zx + 2 * 2048;              // [32][64]

    const int tx = threadIdx.x;
    const int cta = blockIdx.x;        // 0..127
    const int dir = cta >> 6;
    const int hbase = (cta & 63) * 8;
    const float* __restrict__ Wr = dir ? Wbr : Wfr;

    // Pre-split + fragment-pack resident Wr slice.
    // e -> (wmi, kstep, lane, j); lane=(grp,tig); frag regs:
    // j0:(m=grp,k=tig) j1:(grp+8,tig) j2:(grp,tig+4) j3:(grp+8,tig+4)
    for (int e = tx; e < WPK_TERM; e += 256) {
        int j = e & 3;
        int lane = (e >> 2) & 31;
        int kstep = (e >> 7) & 63;
        int wmi = e >> 13;
        int grp = lane >> 2, tig = lane & 3;
        int m = wmi * 16 + grp + ((j & 1) ? 8 : 0);
        int k = kstep * 8 + tig + ((j & 2) ? 4 : 0);
        int gate = m >> 3, jc = m & 7;
        float w = Wr[(size_t)k * G4 + gate * HH + hbase + jc];
        unsigned hi = f2tf(w);
        float lo = w - __uint_as_float(hi);
        Wpack[e] = __uint_as_float(hi);
        Wpack[WPK_TERM + e] = __uint_as_float(f2tf(lo));
    }

    // Zero our slice of h buffer 0
    for (int idx = tx; idx < 8 * 64; idx += 256) {
        int hj = idx >> 6, b = idx & 63;
        g_hbuf[0][dir][hbase + hj][b] = 0.f;
    }

    // Warp layout for MMA
    const int lane = tx & 31;
    const int warp = tx >> 5;
    const int wm = warp >> 2;          // 0..1, m0 = wm*16
    const int n0 = (warp & 3) * 16;    // n (batch) base
    const int grp = lane >> 2;         // 0..7
    const int tig = lane & 3;          // 0..3

    // Gate-phase mapping
    const int b_p = tx & 63;
    const int hj0 = tx >> 6;           // 0..3
    const int hj1 = hj0 + 4;
    float c_reg0 = 0.f, c_reg1 = 0.f;

    const unsigned hs_addr = (unsigned)__cvta_generic_to_shared(hs);
    const unsigned zx_addr = (unsigned)__cvta_generic_to_shared(zx);

    float* out_sent = out + (size_t)Bsz * TT * (2 * HH);

    // Barrier init visibility
    __syncthreads();
    if (tx == 0) {
        __threadfence();
        unsigned old = atomicAdd(&g_cnt, 1u);
        if (old == NCTA - 1) { g_cnt = 0; __threadfence(); g_phase = 1; }
        else { while (g_phase < 1u) { } }
        __threadfence();
    }
    __syncthreads();

    // Prefetch zx[t=0] into buffer 0
    {
        const float* xzb = &g_xz[dir][dir ? (TT - 1) : 0][0][0];
        #pragma unroll
        for (int i = 0; i < 2; i++) {
            int s = tx + i * 256;
            int c = s >> 4, off = (s & 15) * 4;
            int gate = c >> 3, jj = c & 7;
            cp16(zx_addr + (c * 64 + off) * 4,
                 xzb + (size_t)(gate * HH + hbase + jj) * Bsz + off);
        }
        cp_commit();
    }

    for (int t = 0; t < TT; t++) {
        const int rb = t & 1, wb = (t + 1) & 1;
        const int tq = dir ? (TT - 1 - t) : t;
        const int zb = t & 1;                          // zx buffer for this step
        const float* hsrc = &g_hbuf[rb][dir][0][0];    // [512][64] contiguous

        // Issue h chunks 0 and 1 (double-buffered, padded pitch 72)
        #pragma unroll
        for (int i = 0; i < 8; i++) {
            int f4 = tx + i * 256;                 // 0..2047
            int k = f4 >> 4;                       // 0..127
            int b4 = (f4 & 15) * 4;                // 0..60
            cp16(hs_addr + (k * HB_PITCH + b4) * 4, hsrc + k * 64 + b4);
        }
        cp_commit();
        #pragma unroll
        for (int i = 0; i < 8; i++) {
            int f4 = tx + i * 256;
            int k = f4 >> 4;
            int b4 = (f4 & 15) * 4;
            cp16(hs_addr + (HS_CHUNK + k * HB_PITCH + b4) * 4,
                 hsrc + 8192 + k * 64 + b4);
        }
        cp_commit();

        float acc[2][4];
        #pragma unroll
        for (int nt = 0; nt < 2; nt++)
            #pragma unroll
            for (int d = 0; d < 4; d++) acc[nt][d] = 0.f;

        #pragma unroll 1
        for (int ch = 0; ch < 4; ch++) {
            if (ch < 3) cp_wait<1>(); else cp_wait<0>();
            __syncthreads();
            const float* hc = hs + (ch & 1) * HS_CHUNK;
            const float* WH = Wpack + (wm * 64 + ch * 16) * 128;
            const float* WL = WH + WPK_TERM;

            #pragma unroll
            for (int ks = 0; ks < 16; ks++) {
                const int kr = ks * 8;
                uint4 AH = *(const uint4*)(WH + ks * 128 + lane * 4);
                uint4 AL = *(const uint4*)(WL + ks * 128 + lane * 4);
                #pragma unroll
                for (int nt = 0; nt < 2; nt++) {
                    int n = n0 + nt * 8 + grp;
                    float f0 = hc[(kr + tig) * HB_PITCH + n];
                    float f1 = hc[(kr + tig + 4) * HB_PITCH + n];
                    unsigned bh0 = f2tf(f0);
                    unsigned bh1 = f2tf(f1);
                    unsigned bl0 = f2tf(f0 - __uint_as_float(bh0));
                    unsigned bl1 = f2tf(f1 - __uint_as_float(bh1));
                    mma1688(acc[nt], AH.x, AH.y, AH.z, AH.w, bh0, bh1);
                    mma1688(acc[nt], AL.x, AL.y, AL.z, AL.w, bh0, bh1);
                    mma1688(acc[nt], AH.x, AH.y, AH.z, AH.w, bl0, bl1);
                }
            }
            __syncthreads();   // chunk reads done before buffer reuse
            if (ch < 2) {      // issue chunk ch+2 into buffer (ch&1)
                const float* src = hsrc + (ch + 2) * 8192;
                unsigned dstb = hs_addr + (ch & 1) * HS_CHUNK * 4;
                #pragma unroll
                for (int i = 0; i < 8; i++) {
                    int f4 = tx + i * 256;
                    int k = f4 >> 4;
                    int b4 = (f4 & 15) * 4;
                    cp16(dstb + (k * HB_PITCH + b4) * 4, src + k * 64 + b4);
                }
                // Fold next-step zx prefetch into the second refill group
                if (ch == 1 && t < TT - 1) {
                    const int tq2 = dir ? (TT - 2 - t) : (t + 1);
                    const float* xzb = &g_xz[dir][tq2][0][0];
                    unsigned zdst = zx_addr + ((t + 1) & 1) * 2048 * 4;
                    #pragma unroll
                    for (int i = 0; i < 2; i++) {
                        int s = tx + i * 256;
                        int c = s >> 4, off = (s & 15) * 4;
                        int gate = c >> 3, jj = c & 7;
                        cp16(zdst + (c * 64 + off) * 4,
                             xzb + (size_t)(gate * HH + hbase + jj) * Bsz + off);
                    }
                }
                cp_commit();
            }
        }

        // Write acc into zbuf[c][b]  (c = m index = gate*8+j)
        {
            int m0 = wm * 16;
            #pragma unroll
            for (int nt = 0; nt < 2; nt++) {
                int n = n0 + nt * 8 + tig * 2;
                *(float2*)&zbuf[(m0 + grp) * 64 + n] =
                    make_float2(acc[nt][0], acc[nt][1]);
                *(float2*)&zbuf[(m0 + grp + 8) * 64 + n] =
                    make_float2(acc[nt][2], acc[nt][3]);
            }
        }
        __syncthreads();

        // Gate phase
        const float* zxc = zx + zb * 2048;
        float z0[4], z1[4];
        #pragma unroll
        for (int gate = 0; gate < 4; gate++) {
            int c0i = (gate * 8 + hj0) * 64 + b_p;
            int c1i = (gate * 8 + hj1) * 64 + b_p;
            z0[gate] = zxc[c0i] + zbuf[c0i];
            z1[gate] = zxc[c1i] + zbuf[c1i];
        }
        float i0 = sigf(z0[0]), f0 = sigf(z0[1]), g0 = tanhf(z0[2]), o0 = sigf(z0[3]);
        c_reg0 = f0 * c_reg0 + i0 * g0;
        float h0v = o0 * tanhf(c_reg0);
        float i1 = sigf(z1[0]), f1 = sigf(z1[1]), g1 = tanhf(z1[2]), o1 = sigf(z1[3]);
        c_reg1 = f1 * c_reg1 + i1 * g1;
        float h1v = o1 * tanhf(c_reg1);

        // Publish h for next step (coalesced, small) — must precede arrive
        g_hbuf[wb][dir][hbase + hj0][b_p] = h0v;
        g_hbuf[wb][dir][hbase + hj1][b_p] = h1v;

        if (t < TT - 1) {
            // ---- barrier ARRIVE (fence drains only the small hbuf stores) ----
            __syncthreads();
            if (tx == 0) {
                __threadfence();
                unsigned old = atomicAdd(&g_cnt, 1u);
                if (old == NCTA - 1) {
                    g_cnt = 0;
                    __threadfence();
                    g_phase = (unsigned)(t + 2);
                }
            }
            // ---- scattered output stores overlap the wait ----
            size_t wo = ((size_t)b_p * TT + tq) * (2 * HH) + dir * HH + hbase;
            out[wo + hj0] = h0v;
            out[wo + hj1] = h1v;
            // ---- barrier WAIT ----
            if (tx == 0) {
                while (g_phase < (unsigned)(t + 2)) { }
                __threadfence();
            }
            __syncthreads();
        } else {
            size_t wo = ((size_t)b_p * TT + tq) * (2 * HH) + dir * HH + hbase;
            out[wo + hj0] = h0v;
            out[wo + hj1] = h1v;
            size_t so = (size_t)b_p * (2 * HH) + dir * HH + hbase;
            out_sent[so + hj0] = h0v;
            out_sent[so + hj1] = h1v;
        }
    }

    // Reset barrier state for next graph replay
    __syncthreads();
    if (tx == 0) {
        __threadfence();
        unsigned old = atomicAdd(&g_cnt, 1u);
        if (old == NCTA - 1) {
            g_cnt = 0;
            __threadfence();
            g_phase = 0;
        }
    }
}

// ---------------------------------------------------------------------------
extern "C" void kernel_launch(void* const* d_in, const int* in_sizes, int n_in,
                              void* d_out, int out_size) {
    const float* x   = (const float*)d_in[0];
    const float* Wfk = (const float*)d_in[1];
    const float* Wfr = (const float*)d_in[2];
    const float* bf  = (const float*)d_in[3];
    const float* Wbk = (const float*)d_in[4];
    const float* Wbr = (const float*)d_in[5];
    const float* bb  = (const float*)d_in[6];
    float* out = (float*)d_out;

    cudaFuncSetAttribute(scan_mma_kernel,
                         cudaFuncAttributeMaxDynamicSharedMemorySize, SCAN_SMEM);
    cudaFuncSetAttribute(proj_mma_kernel,
                         cudaFuncAttributeMaxDynamicSharedMemorySize, PROJ_SMEM);

    dim3 pg(8, 256, 2);
    proj_mma_kernel<<<pg, 512, PROJ_SMEM>>>(x, Wfk, bf, Wbk, bb);
    scan_mma_kernel<<<NCTA, 256, SCAN_SMEM>>>(Wfr, Wbr, out);
}